// round 12
// baseline (speedup 1.0000x reference)
#include <cuda_runtime.h>
#include <cuda_fp16.h>
#include <cstdint>

// Problem constants
#define B_  4
#define L_  4096
#define H_  1024
#define U_  1024
#define M_  (B_*L_)          // 16384 rows

constexpr int CL = 64;            // scan chunk length
constexpr int NC = L_ / CL;       // 64 chunks per sequence

// ---------------- scratch (device globals; no allocation allowed) -------------
__device__ __half g_inH[(size_t)M_ * H_];   // fp16 inputs          (32 MB)
__device__ __half g_WiH[(size_t)U_ * H_];   // fp16 Wi              (2 MB)
__device__ __half g_WoH[(size_t)H_ * U_];   // fp16 Wo              (2 MB)
__device__ __half g_uh [(size_t)M_ * U_];   // fp16 u, then scanned x (32 MB)
__device__ float  g_v  [(size_t)B_ * NC * U_]; // chunk carries      (1 MB)
__device__ unsigned g_cnt[2];               // grid-barrier counters (reset by cvt)

// ---------------- helpers ----------------------------------------------------
__device__ __forceinline__ uint32_t smem_u32(const void* p) {
    uint32_t a;
    asm("{ .reg .u64 t; cvta.to.shared.u64 t, %1; cvt.u32.u64 %0, t; }"
        : "=r"(a) : "l"(p));
    return a;
}

__device__ __forceinline__ void cp16(uint32_t saddr, const void* g) {
    asm volatile("cp.async.cg.shared.global [%0], [%1], 16;" :: "r"(saddr), "l"(g));
}
__device__ __forceinline__ void cp_commit() {
    asm volatile("cp.async.commit_group;" ::: "memory");
}

// ldmatrix x4: 4 matrices of 8 rows x 16B (8 halves).
__device__ __forceinline__ void ldsm4(uint32_t* r, uint32_t addr) {
    asm volatile("ldmatrix.sync.aligned.m8n8.x4.shared.b16 {%0,%1,%2,%3}, [%4];"
                 : "=r"(r[0]), "=r"(r[1]), "=r"(r[2]), "=r"(r[3]) : "r"(addr));
}

// fp32-accumulate MMA (used by GEMM2)
__device__ __forceinline__ void mma_f16(float* d, const uint32_t* a, const uint32_t* b) {
    asm volatile(
        "mma.sync.aligned.m16n8k16.row.col.f32.f16.f16.f32 "
        "{%0,%1,%2,%3}, {%4,%5,%6,%7}, {%8,%9}, {%0,%1,%2,%3};\n"
        : "+f"(d[0]), "+f"(d[1]), "+f"(d[2]), "+f"(d[3])
        : "r"(a[0]), "r"(a[1]), "r"(a[2]), "r"(a[3]),
          "r"(b[0]), "r"(b[1]));
}

// fp16-accumulate MMA (used by GEMM1; 2x rate hypothesis)
__device__ __forceinline__ void mma_f16acc(uint32_t* d, const uint32_t* a, const uint32_t* b) {
    asm volatile(
        "mma.sync.aligned.m16n8k16.row.col.f16.f16.f16.f16 "
        "{%0,%1}, {%2,%3,%4,%5}, {%6,%7}, {%0,%1};\n"
        : "+r"(d[0]), "+r"(d[1])
        : "r"(a[0]), "r"(a[1]), "r"(a[2]), "r"(a[3]),
          "r"(b[0]), "r"(b[1]));
}

// device-wide spin barrier (all gridDim.x blocks must be co-resident)
__device__ __forceinline__ void grid_bar(unsigned* cnt) {
    __syncthreads();
    if (threadIdx.x == 0) {
        __threadfence();
        atomicAdd(cnt, 1u);
        while (*(volatile unsigned*)cnt < gridDim.x) { __nanosleep(32); }
    }
    __syncthreads();
    __threadfence();
}

// ---------------- fused fp16 conversion (inputs + Wi + Wo) --------------------
__global__ void cvt_all_kernel(const float4* __restrict__ in,
                               const float4* __restrict__ wi,
                               const float4* __restrict__ wo)
{
    if (blockIdx.x == 0 && threadIdx.x == 0) {   // reset scan grid-barriers
        g_cnt[0] = 0;
        g_cnt[1] = 0;
    }
    const size_t n_in = (size_t)M_ * H_ / 8;    // uint4 (8-half) chunks
    const size_t n_w  = (size_t)U_ * H_ / 8;
    const size_t n_tot = n_in + 2 * n_w;
    size_t i = (size_t)blockIdx.x * blockDim.x + threadIdx.x;
    const size_t stride = (size_t)gridDim.x * blockDim.x;
    for (; i < n_tot; i += stride) {
        const float4* src;
        __half* dst;
        size_t j;
        if (i < n_in)            { src = in; dst = g_inH; j = i; }
        else if (i < n_in + n_w) { src = wi; dst = g_WiH; j = i - n_in; }
        else                     { src = wo; dst = g_WoH; j = i - n_in - n_w; }
        float4 a = src[2 * j], b = src[2 * j + 1];
        __half2 h[4];
        h[0] = __floats2half2_rn(a.x, a.y);
        h[1] = __floats2half2_rn(a.z, a.w);
        h[2] = __floats2half2_rn(b.x, b.y);
        h[3] = __floats2half2_rn(b.z, b.w);
        reinterpret_cast<uint4*>(dst)[j] = *reinterpret_cast<uint4*>(h);
    }
}

// ---------------- GEMM geometry (shared) -------------------------------------
constexpr int TM = 128, TN = 128, BKH = 64;   // BKH in halves
constexpr int KDIM = 1024;                    // halves
constexpr int NKT  = KDIM / BKH;              // 16 chunks
constexpr int NSTAGE = 3;
constexpr int STAGE_A   = TM * 128;           // 16384 B per operand tile
constexpr int STAGE_TOT = 2 * STAGE_A;        // 32768 B
constexpr int GEMM_SMEM = NSTAGE * STAGE_TOT; // 98304 B

// ---------------- GEMM1: u = inputs*Wi^T + bi -> g_uh (fp16) -----------------
// fp16-accumulate MMAs, fp32 promotion every 2 k16-steps.
__global__ __launch_bounds__(256, 2)
void gemm1_kernel(const float* __restrict__ bias)
{
    extern __shared__ char smem[];
    const uint32_t sb = smem_u32(smem);
    const int tid = threadIdx.x;
    const int warp = tid >> 5, lane = tid & 31;

    const __half* __restrict__ A  = g_inH;
    const __half* __restrict__ Bw = g_WiH;
    const int bm = blockIdx.y * TM;
    const int bn = blockIdx.x * TN;

    const int wm = (warp >> 1) * 32;      // warp M offset
    const int wn = (warp & 1) * 64;       // warp N offset

    const int srow = tid >> 1;            // 0..127
    const int gb0  = (tid & 1) * 4;       // chunk base 0 or 4
    uint32_t swoff[4];
    #pragma unroll
    for (int i = 0; i < 4; i++)
        swoff[i] = (uint32_t)srow * 128u + ((uint32_t)((gb0 + i) ^ (srow & 7)) << 4);
    const __half* Arow = A  + (size_t)(bm + srow) * KDIM;
    const __half* Brow = Bw + (size_t)(bn + srow) * KDIM;

    const int lrA  = lane & 15;
    const int gsA  = lane >> 4;
    const int lrB  = ((lane & 16) >> 1) + (lane & 7);
    const int gsB  = (lane >> 3) & 1;

    float acc[2][8][4];
    #pragma unroll
    for (int mt = 0; mt < 2; mt++)
        #pragma unroll
        for (int nt = 0; nt < 8; nt++)
            #pragma unroll
            for (int i = 0; i < 4; i++) acc[mt][nt][i] = 0.f;

    #pragma unroll
    for (int c = 0; c < NSTAGE - 1; c++) {
        const uint32_t ao = sb + c * STAGE_TOT;
        #pragma unroll
        for (int i = 0; i < 4; i++) {
            cp16(ao + swoff[i], Arow + c * BKH + (gb0 + i) * 8);
            cp16(ao + STAGE_A + swoff[i], Brow + c * BKH + (gb0 + i) * 8);
        }
        cp_commit();
    }

    #pragma unroll 1
    for (int kt = 0; kt < NKT; kt++) {
        asm volatile("cp.async.wait_group 1;" ::: "memory");
        __syncthreads();

        if (kt + 2 < NKT) {
            const uint32_t ao = sb + ((kt + 2) % NSTAGE) * STAGE_TOT;
            const int k0 = (kt + 2) * BKH;
            #pragma unroll
            for (int i = 0; i < 4; i++) {
                cp16(ao + swoff[i], Arow + k0 + (gb0 + i) * 8);
                cp16(ao + STAGE_A + swoff[i], Brow + k0 + (gb0 + i) * 8);
            }
        }
        cp_commit();

        const uint32_t sA = sb + (kt % NSTAGE) * STAGE_TOT;
        const uint32_t sB = sA + STAGE_A;

        #pragma unroll
        for (int ksp = 0; ksp < 2; ksp++) {   // 2 windows of 2 k16-steps
            uint32_t afr[2][2][4], bfr[4][2][4];
            #pragma unroll
            for (int mt = 0; mt < 2; mt++)
                #pragma unroll
                for (int j = 0; j < 2; j++) {
                    const int ks = ksp * 2 + j;
                    const int r = wm + mt * 16 + lrA;
                    const uint32_t g = (uint32_t)((ks * 2 + gsA) ^ (lrA & 7));
                    ldsm4(afr[mt][j], sA + (uint32_t)r * 128u + (g << 4));
                }
            #pragma unroll
            for (int p = 0; p < 4; p++)
                #pragma unroll
                for (int j = 0; j < 2; j++) {
                    const int ks = ksp * 2 + j;
                    const int r = wn + p * 16 + lrB;
                    const uint32_t g = (uint32_t)((ks * 2 + gsB) ^ (lrB & 7));
                    ldsm4(bfr[p][j], sB + (uint32_t)r * 128u + (g << 4));
                }
            #pragma unroll
            for (int mt = 0; mt < 2; mt++)
                #pragma unroll
                for (int nt = 0; nt < 8; nt++) {
                    uint32_t d16[2] = {0u, 0u};
                    #pragma unroll
                    for (int j = 0; j < 2; j++)
                        mma_f16acc(d16, afr[mt][j], &bfr[nt >> 1][j][(nt & 1) * 2]);
                    const float2 f0 = __half22float2(*reinterpret_cast<__half2*>(&d16[0]));
                    const float2 f1 = __half22float2(*reinterpret_cast<__half2*>(&d16[1]));
                    acc[mt][nt][0] += f0.x;
                    acc[mt][nt][1] += f0.y;
                    acc[mt][nt][2] += f1.x;
                    acc[mt][nt][3] += f1.y;
                }
        }
    }

    // epilogue: add bias, write fp16 to g_uh
    const int gid = lane >> 2, t4 = lane & 3;
    #pragma unroll
    for (int mt = 0; mt < 2; mt++) {
        const int row = bm + wm + mt * 16 + gid;
        #pragma unroll
        for (int nt = 0; nt < 8; nt++) {
            const int col = bn + wn + nt * 8 + t4 * 2;
            const float b0 = bias[col], b1 = bias[col + 1];
            __half2 v0 = __floats2half2_rn(acc[mt][nt][0] + b0, acc[mt][nt][1] + b1);
            __half2 v1 = __floats2half2_rn(acc[mt][nt][2] + b0, acc[mt][nt][3] + b1);
            *reinterpret_cast<__half2*>(&g_uh[(size_t)row * 1024 + col]) = v0;
            *reinterpret_cast<__half2*>(&g_uh[(size_t)(row + 8) * 1024 + col]) = v1;
        }
    }
}

// ---------------- GEMM2: out = x*Wo^T + bo (fp32 accum, unchanged) -----------
__global__ __launch_bounds__(256, 2)
void gemm2_kernel(const float* __restrict__ bias, float* __restrict__ Cext)
{
    extern __shared__ char smem[];
    const uint32_t sb = smem_u32(smem);
    const int tid = threadIdx.x;
    const int warp = tid >> 5, lane = tid & 31;

    const __half* __restrict__ A  = g_uh;
    const __half* __restrict__ Bw = g_WoH;
    const int bm = blockIdx.y * TM;
    const int bn = blockIdx.x * TN;

    const int wm = (warp >> 1) * 32;
    const int wn = (warp & 1) * 64;

    const int srow = tid >> 1;
    const int gb0  = (tid & 1) * 4;
    uint32_t swoff[4];
    #pragma unroll
    for (int i = 0; i < 4; i++)
        swoff[i] = (uint32_t)srow * 128u + ((uint32_t)((gb0 + i) ^ (srow & 7)) << 4);
    const __half* Arow = A  + (size_t)(bm + srow) * KDIM;
    const __half* Brow = Bw + (size_t)(bn + srow) * KDIM;

    const int lrA  = lane & 15;
    const int gsA  = lane >> 4;
    const int lrB  = ((lane & 16) >> 1) + (lane & 7);
    const int gsB  = (lane >> 3) & 1;

    float acc[2][8][4];
    #pragma unroll
    for (int mt = 0; mt < 2; mt++)
        #pragma unroll
        for (int nt = 0; nt < 8; nt++)
            #pragma unroll
            for (int i = 0; i < 4; i++) acc[mt][nt][i] = 0.f;

    #pragma unroll
    for (int c = 0; c < NSTAGE - 1; c++) {
        const uint32_t ao = sb + c * STAGE_TOT;
        #pragma unroll
        for (int i = 0; i < 4; i++) {
            cp16(ao + swoff[i], Arow + c * BKH + (gb0 + i) * 8);
            cp16(ao + STAGE_A + swoff[i], Brow + c * BKH + (gb0 + i) * 8);
        }
        cp_commit();
    }

    #pragma unroll 1
    for (int kt = 0; kt < NKT; kt++) {
        asm volatile("cp.async.wait_group 1;" ::: "memory");
        __syncthreads();

        if (kt + 2 < NKT) {
            const uint32_t ao = sb + ((kt + 2) % NSTAGE) * STAGE_TOT;
            const int k0 = (kt + 2) * BKH;
            #pragma unroll
            for (int i = 0; i < 4; i++) {
                cp16(ao + swoff[i], Arow + k0 + (gb0 + i) * 8);
                cp16(ao + STAGE_A + swoff[i], Brow + k0 + (gb0 + i) * 8);
            }
        }
        cp_commit();

        const uint32_t sA = sb + (kt % NSTAGE) * STAGE_TOT;
        const uint32_t sB = sA + STAGE_A;

        #pragma unroll
        for (int ks = 0; ks < 4; ks++) {
            uint32_t afr[2][4], bfr[4][4];
            #pragma unroll
            for (int mt = 0; mt < 2; mt++) {
                const int r = wm + mt * 16 + lrA;
                const uint32_t g = (uint32_t)((ks * 2 + gsA) ^ (lrA & 7));
                ldsm4(afr[mt], sA + (uint32_t)r * 128u + (g << 4));
            }
            #pragma unroll
            for (int p = 0; p < 4; p++) {
                const int r = wn + p * 16 + lrB;
                const uint32_t g = (uint32_t)((ks * 2 + gsB) ^ (lrB & 7));
                ldsm4(bfr[p], sB + (uint32_t)r * 128u + (g << 4));
            }
            #pragma unroll
            for (int mt = 0; mt < 2; mt++)
                #pragma unroll
                for (int nt = 0; nt < 8; nt++)
                    mma_f16(acc[mt][nt], afr[mt], &bfr[nt >> 1][(nt & 1) * 2]);
        }
    }

    const int gid = lane >> 2, t4 = lane & 3;
    #pragma unroll
    for (int mt = 0; mt < 2; mt++) {
        const int row = bm + wm + mt * 16 + gid;
        #pragma unroll
        for (int nt = 0; nt < 8; nt++) {
            const int col = bn + wn + nt * 8 + t4 * 2;
            const float b0 = bias[col], b1 = bias[col + 1];
            float2 v0 = make_float2(acc[mt][nt][0] + b0, acc[mt][nt][1] + b1);
            float2 v1 = make_float2(acc[mt][nt][2] + b0, acc[mt][nt][3] + b1);
            *reinterpret_cast<float2*>(&Cext[(size_t)row * 1024 + col]) = v0;
            *reinterpret_cast<float2*>(&Cext[(size_t)(row + 8) * 1024 + col]) = v1;
        }
    }
}

// ---------------- fused scan: agg -> carry -> apply, one kernel ---------------
__global__ __launch_bounds__(256)
void scan_fused_kernel(const float* __restrict__ plog)
{
    const int tid = threadIdx.x;

    // ---- phase 1: chunk aggregates -> g_v (2 u's per thread, half2) ----
    {
        const int g  = blockIdx.x * 256 + tid;
        const int u2 = g & (U_ / 2 - 1);
        const int c  = (g >> 9) & (NC - 1);
        const int b  = g >> 15;
        const int uu = u2 * 2;
        const float lam0 = expf(-expf(plog[uu]));
        const float lam1 = expf(-expf(plog[uu + 1]));
        const __half2* p = reinterpret_cast<const __half2*>(
            g_uh + (size_t)(b * L_ + c * CL) * U_) + u2;
        float h0 = 0.f, h1 = 0.f;
        #pragma unroll 8
        for (int t = 0; t < CL; t++) {
            float2 v = __half22float2(p[(size_t)t * (U_ / 2)]);
            h0 = fmaf(lam0, h0, v.x);
            h1 = fmaf(lam1, h1, v.y);
        }
        reinterpret_cast<float2*>(g_v + (size_t)(b * NC + c) * U_)[u2] =
            make_float2(h0, h1);
    }

    grid_bar(&g_cnt[0]);

    // ---- phase 2: exclusive scan of aggregates (one warp per (b,u)) ----
    {
        const int idx  = blockIdx.x * 256 + tid;
        const int lane = idx & 31;
        const int w    = idx >> 5;
        const int uu   = w & (U_ - 1);
        const int b    = w >> 10;
        const float nu   = expf(plog[uu]);
        const float lamC = expf(-(float)CL * nu);
        float* pv = g_v + (size_t)b * NC * U_ + uu;

        const float a0 = pv[(size_t)(2 * lane) * U_];
        const float a1 = pv[(size_t)(2 * lane + 1) * U_];
        float p = fmaf(lamC, a0, a1);
        const float lamC2 = lamC * lamC;

        float mult = lamC2;
        #pragma unroll
        for (int s = 1; s < 32; s <<= 1) {
            float other = __shfl_up_sync(0xffffffffu, p, s);
            if (lane >= s) p = fmaf(mult, other, p);
            mult = mult * mult;
        }

        const float Pprev = __shfl_up_sync(0xffffffffu, p, 1);
        const float E0 = (lane == 0) ? 0.f : Pprev;
        const float E1 = fmaf(lamC, E0, a0);
        pv[(size_t)(2 * lane) * U_]     = E0;
        pv[(size_t)(2 * lane + 1) * U_] = E1;
    }

    grid_bar(&g_cnt[1]);

    // ---- phase 3: redo local scan seeded with carry, * gamma, in place ----
    {
        const int g  = blockIdx.x * 256 + tid;
        const int u2 = g & (U_ / 2 - 1);
        const int c  = (g >> 9) & (NC - 1);
        const int b  = g >> 15;
        const int uu = u2 * 2;
        const float lam0 = expf(-expf(plog[uu]));
        const float lam1 = expf(-expf(plog[uu + 1]));
        const float gam0 = expf(plog[U_ + uu]);
        const float gam1 = expf(plog[U_ + uu + 1]);
        float2 h = reinterpret_cast<const float2*>(
            g_v + (size_t)(b * NC + c) * U_)[u2];
        __half2* p = reinterpret_cast<__half2*>(
            g_uh + (size_t)(b * L_ + c * CL) * U_) + u2;
        #pragma unroll 8
        for (int t = 0; t < CL; t++) {
            float2 v = __half22float2(p[(size_t)t * (U_ / 2)]);
            h.x = fmaf(lam0, h.x, v.x);
            h.y = fmaf(lam1, h.y, v.y);
            p[(size_t)t * (U_ / 2)] = __floats2half2_rn(h.x * gam0, h.y * gam1);
        }
    }
}

// ---------------- launch ------------------------------------------------------
extern "C" void kernel_launch(void* const* d_in, const int* in_sizes, int n_in,
                              void* d_out, int out_size)
{
    const float* inputs = (const float*)d_in[0];
    const float* Wi     = (const float*)d_in[1];
    const float* bi     = (const float*)d_in[2];
    const float* Wo     = (const float*)d_in[3];
    const float* bo     = (const float*)d_in[4];
    const float* plog   = (const float*)d_in[5];
    float* out = (float*)d_out;

    cudaFuncSetAttribute(gemm1_kernel,
                         cudaFuncAttributeMaxDynamicSharedMemorySize, GEMM_SMEM);
    cudaFuncSetAttribute(gemm2_kernel,
                         cudaFuncAttributeMaxDynamicSharedMemorySize, GEMM_SMEM);

    // fp16 conversion (also resets the scan grid-barrier counters)
    cvt_all_kernel<<<2048, 256>>>((const float4*)inputs,
                                  (const float4*)Wi,
                                  (const float4*)Wo);

    // GEMM1: u = inputs * Wi^T + bi   -> g_uh (fp16), fp16-accum MMAs
    gemm1_kernel<<<dim3(U_ / TN, M_ / TM), 256, GEMM_SMEM>>>(bi);

    // fused scan (agg -> carry -> apply), in place on g_uh
    scan_fused_kernel<<<(B_ * NC * U_ / 2) / 256, 256>>>(plog);

    // GEMM2: out = x * Wo^T + bo, fp32-accum MMAs
    gemm2_kernel<<<dim3(H_ / TN, M_ / TM), 256, GEMM_SMEM>>>(bo, out);
}

// round 13
// speedup vs baseline: 1.4353x; 1.4353x over previous
#include <cuda_runtime.h>
#include <cuda_fp16.h>
#include <cstdint>

// Problem constants
#define B_  4
#define L_  4096
#define H_  1024
#define U_  1024
#define M_  (B_*L_)          // 16384 rows

constexpr int CL = 64;            // scan chunk length
constexpr int NC = L_ / CL;       // 64 chunks per sequence

// ---------------- scratch (device globals; no allocation allowed) -------------
__device__ __half g_inH[(size_t)M_ * H_];   // fp16 inputs          (32 MB)
__device__ __half g_WiH[(size_t)U_ * H_];   // fp16 Wi              (2 MB)
__device__ __half g_WoH[(size_t)H_ * U_];   // fp16 Wo              (2 MB)
__device__ __half g_uh [(size_t)M_ * U_];   // fp16 u, then scanned x (32 MB)
__device__ float  g_v  [(size_t)B_ * NC * U_]; // chunk carries      (1 MB)
__device__ unsigned g_cnt[2];               // grid-barrier counters (reset by cvt)

// ---------------- helpers ----------------------------------------------------
__device__ __forceinline__ uint32_t smem_u32(const void* p) {
    uint32_t a;
    asm("{ .reg .u64 t; cvta.to.shared.u64 t, %1; cvt.u32.u64 %0, t; }"
        : "=r"(a) : "l"(p));
    return a;
}

__device__ __forceinline__ void cp16(uint32_t saddr, const void* g) {
    asm volatile("cp.async.cg.shared.global [%0], [%1], 16;" :: "r"(saddr), "l"(g));
}
__device__ __forceinline__ void cp_commit() {
    asm volatile("cp.async.commit_group;" ::: "memory");
}

// ldmatrix x4: 4 matrices of 8 rows x 16B (8 halves).
__device__ __forceinline__ void ldsm4(uint32_t* r, uint32_t addr) {
    asm volatile("ldmatrix.sync.aligned.m8n8.x4.shared.b16 {%0,%1,%2,%3}, [%4];"
                 : "=r"(r[0]), "=r"(r[1]), "=r"(r[2]), "=r"(r[3]) : "r"(addr));
}

// fp32-accumulate MMA
__device__ __forceinline__ void mma_f16(float* d, const uint32_t* a, const uint32_t* b) {
    asm volatile(
        "mma.sync.aligned.m16n8k16.row.col.f32.f16.f16.f32 "
        "{%0,%1,%2,%3}, {%4,%5,%6,%7}, {%8,%9}, {%0,%1,%2,%3};\n"
        : "+f"(d[0]), "+f"(d[1]), "+f"(d[2]), "+f"(d[3])
        : "r"(a[0]), "r"(a[1]), "r"(a[2]), "r"(a[3]),
          "r"(b[0]), "r"(b[1]));
}

// device-wide spin barrier (all gridDim.x blocks must be co-resident)
__device__ __forceinline__ void grid_bar(unsigned* cnt) {
    __syncthreads();
    if (threadIdx.x == 0) {
        __threadfence();
        atomicAdd(cnt, 1u);
        while (*(volatile unsigned*)cnt < gridDim.x) { __nanosleep(32); }
    }
    __syncthreads();
    __threadfence();
}

// ---------------- fused fp16 conversion (inputs + Wi + Wo) --------------------
__global__ void cvt_all_kernel(const float4* __restrict__ in,
                               const float4* __restrict__ wi,
                               const float4* __restrict__ wo)
{
    if (blockIdx.x == 0 && threadIdx.x == 0) {   // reset scan grid-barriers
        g_cnt[0] = 0;
        g_cnt[1] = 0;
    }
    const size_t n_in = (size_t)M_ * H_ / 8;    // uint4 (8-half) chunks
    const size_t n_w  = (size_t)U_ * H_ / 8;
    const size_t n_tot = n_in + 2 * n_w;
    size_t i = (size_t)blockIdx.x * blockDim.x + threadIdx.x;
    const size_t stride = (size_t)gridDim.x * blockDim.x;
    for (; i < n_tot; i += stride) {
        const float4* src;
        __half* dst;
        size_t j;
        if (i < n_in)            { src = in; dst = g_inH; j = i; }
        else if (i < n_in + n_w) { src = wi; dst = g_WiH; j = i - n_in; }
        else                     { src = wo; dst = g_WoH; j = i - n_in - n_w; }
        float4 a = src[2 * j], b = src[2 * j + 1];
        __half2 h[4];
        h[0] = __floats2half2_rn(a.x, a.y);
        h[1] = __floats2half2_rn(a.z, a.w);
        h[2] = __floats2half2_rn(b.x, b.y);
        h[3] = __floats2half2_rn(b.z, b.w);
        reinterpret_cast<uint4*>(dst)[j] = *reinterpret_cast<uint4*>(h);
    }
}

// ---------------- FP16 mma GEMM: C = A*B^T + bias ----------------------------
// CTA tile 128(M) x 64(N), 8 warps (4M x 2N), warp tile 32x32, BK=64 halves
// (=128B rows), 3-stage cp.async, mma m16n8k16, fp32 accum. 3 CTAs/SM.
// sel==0: A=g_inH, B=g_WiH, C=g_uh (fp16).  sel==1: A=g_uh, B=g_WoH, C=out(fp32).
constexpr int TM = 128, TN = 64, BKH = 64;    // BKH in halves
constexpr int KDIM = 1024;                    // halves
constexpr int NKT  = KDIM / BKH;              // 16 chunks
constexpr int NSTAGE = 3;
constexpr int STAGE_A   = TM * 128;           // 16384 B (A tile)
constexpr int STAGE_B   = TN * 128;           // 8192 B  (B tile)
constexpr int STAGE_TOT = STAGE_A + STAGE_B;  // 24576 B
constexpr int GEMM_SMEM = NSTAGE * STAGE_TOT; // 73728 B

__global__ __launch_bounds__(256, 3)
void gemm_f16_kernel(int sel, const float* __restrict__ bias, float* __restrict__ Cext)
{
    extern __shared__ char smem[];
    const uint32_t sb = smem_u32(smem);
    const int tid = threadIdx.x;
    const int warp = tid >> 5, lane = tid & 31;

    const __half* __restrict__ A  = sel ? g_uh  : g_inH;
    const __half* __restrict__ Bw = sel ? g_WoH : g_WiH;
    const int bm = blockIdx.y * TM;
    const int bn = blockIdx.x * TN;

    const int wm = (warp >> 1) * 32;      // warp M offset (0..96)
    const int wn = (warp & 1) * 32;       // warp N offset (0/32)

    // ---- staging: thread -> (row group, 16B chunk). 32 rows per pass. ----
    const int srow = tid >> 3;            // 0..31
    const int gcol = tid & 7;             // 16B chunk in 128B row
    // swizzled offsets for rows srow+32*i
    uint32_t swA[4], swB[2];
    #pragma unroll
    for (int i = 0; i < 4; i++) {
        const int r = srow + 32 * i;
        swA[i] = (uint32_t)r * 128u + ((uint32_t)(gcol ^ (r & 7)) << 4);
    }
    #pragma unroll
    for (int i = 0; i < 2; i++) {
        const int r = srow + 32 * i;
        swB[i] = (uint32_t)r * 128u + ((uint32_t)(gcol ^ (r & 7)) << 4);
    }
    const __half* Arow = A  + (size_t)(bm + srow) * KDIM + gcol * 8;
    const __half* Brow = Bw + (size_t)(bn + srow) * KDIM + gcol * 8;

    // ---- ldmatrix per-lane invariants (x4, non-trans) ----
    const int lrA  = lane & 15;           // A row-in-16
    const int gsA  = lane >> 4;           // A k-chunk select (0/1)
    const int lrB  = ((lane & 16) >> 1) + (lane & 7);   // B row offset 0..15
    const int gsB  = (lane >> 3) & 1;     // B k-chunk select

    float acc[2][4][4];
    #pragma unroll
    for (int mt = 0; mt < 2; mt++)
        #pragma unroll
        for (int nt = 0; nt < 4; nt++)
            #pragma unroll
            for (int i = 0; i < 4; i++) acc[mt][nt][i] = 0.f;

    // ---- prologue: stage chunks 0,1 ----
    #pragma unroll
    for (int c = 0; c < NSTAGE - 1; c++) {
        const uint32_t ao = sb + c * STAGE_TOT;
        #pragma unroll
        for (int i = 0; i < 4; i++)
            cp16(ao + swA[i], Arow + (size_t)(32 * i) * KDIM + c * BKH);
        #pragma unroll
        for (int i = 0; i < 2; i++)
            cp16(ao + STAGE_A + swB[i], Brow + (size_t)(32 * i) * KDIM + c * BKH);
        cp_commit();
    }

    #pragma unroll 1
    for (int kt = 0; kt < NKT; kt++) {
        asm volatile("cp.async.wait_group 1;" ::: "memory");
        __syncthreads();

        if (kt + 2 < NKT) {
            const uint32_t ao = sb + ((kt + 2) % NSTAGE) * STAGE_TOT;
            const int k0 = (kt + 2) * BKH;
            #pragma unroll
            for (int i = 0; i < 4; i++)
                cp16(ao + swA[i], Arow + (size_t)(32 * i) * KDIM + k0);
            #pragma unroll
            for (int i = 0; i < 2; i++)
                cp16(ao + STAGE_A + swB[i], Brow + (size_t)(32 * i) * KDIM + k0);
        }
        cp_commit();

        const uint32_t sA = sb + (kt % NSTAGE) * STAGE_TOT;
        const uint32_t sB = sA + STAGE_A;

        #pragma unroll
        for (int ks = 0; ks < 4; ks++) {          // 4 x k16 per 64-half chunk
            uint32_t afr[2][4], bfr[2][4];
            #pragma unroll
            for (int mt = 0; mt < 2; mt++) {
                const int r = wm + mt * 16 + lrA;
                const uint32_t g = (uint32_t)((ks * 2 + gsA) ^ (lrA & 7));
                ldsm4(afr[mt], sA + (uint32_t)r * 128u + (g << 4));
            }
            #pragma unroll
            for (int p = 0; p < 2; p++) {
                const int r = wn + p * 16 + lrB;
                const uint32_t g = (uint32_t)((ks * 2 + gsB) ^ (lrB & 7));
                ldsm4(bfr[p], sB + (uint32_t)r * 128u + (g << 4));
            }
            #pragma unroll
            for (int mt = 0; mt < 2; mt++)
                #pragma unroll
                for (int nt = 0; nt < 4; nt++)
                    mma_f16(acc[mt][nt], afr[mt], &bfr[nt >> 1][(nt & 1) * 2]);
        }
    }

    // ---- epilogue: add bias; write fp16 (sel=0 -> g_uh) or fp32 (sel=1) ----
    const int gid = lane >> 2, t4 = lane & 3;
    if (sel == 0) {
        #pragma unroll
        for (int mt = 0; mt < 2; mt++) {
            const int row = bm + wm + mt * 16 + gid;
            #pragma unroll
            for (int nt = 0; nt < 4; nt++) {
                const int col = bn + wn + nt * 8 + t4 * 2;
                const float b0 = bias[col], b1 = bias[col + 1];
                __half2 v0 = __floats2half2_rn(acc[mt][nt][0] + b0, acc[mt][nt][1] + b1);
                __half2 v1 = __floats2half2_rn(acc[mt][nt][2] + b0, acc[mt][nt][3] + b1);
                *reinterpret_cast<__half2*>(&g_uh[(size_t)row * 1024 + col]) = v0;
                *reinterpret_cast<__half2*>(&g_uh[(size_t)(row + 8) * 1024 + col]) = v1;
            }
        }
    } else {
        #pragma unroll
        for (int mt = 0; mt < 2; mt++) {
            const int row = bm + wm + mt * 16 + gid;
            #pragma unroll
            for (int nt = 0; nt < 4; nt++) {
                const int col = bn + wn + nt * 8 + t4 * 2;
                const float b0 = bias[col], b1 = bias[col + 1];
                float2 v0 = make_float2(acc[mt][nt][0] + b0, acc[mt][nt][1] + b1);
                float2 v1 = make_float2(acc[mt][nt][2] + b0, acc[mt][nt][3] + b1);
                *reinterpret_cast<float2*>(&Cext[(size_t)row * 1024 + col]) = v0;
                *reinterpret_cast<float2*>(&Cext[(size_t)(row + 8) * 1024 + col]) = v1;
            }
        }
    }
}

// ---------------- fused scan: agg -> carry -> apply, one kernel ---------------
__global__ __launch_bounds__(256)
void scan_fused_kernel(const float* __restrict__ plog)
{
    const int tid = threadIdx.x;

    // ---- phase 1: chunk aggregates -> g_v (2 u's per thread, half2) ----
    {
        const int g  = blockIdx.x * 256 + tid;
        const int u2 = g & (U_ / 2 - 1);
        const int c  = (g >> 9) & (NC - 1);
        const int b  = g >> 15;
        const int uu = u2 * 2;
        const float lam0 = expf(-expf(plog[uu]));
        const float lam1 = expf(-expf(plog[uu + 1]));
        const __half2* p = reinterpret_cast<const __half2*>(
            g_uh + (size_t)(b * L_ + c * CL) * U_) + u2;
        float h0 = 0.f, h1 = 0.f;
        #pragma unroll 8
        for (int t = 0; t < CL; t++) {
            float2 v = __half22float2(p[(size_t)t * (U_ / 2)]);
            h0 = fmaf(lam0, h0, v.x);
            h1 = fmaf(lam1, h1, v.y);
        }
        reinterpret_cast<float2*>(g_v + (size_t)(b * NC + c) * U_)[u2] =
            make_float2(h0, h1);
    }

    grid_bar(&g_cnt[0]);

    // ---- phase 2: exclusive scan of aggregates (one warp per (b,u)) ----
    {
        const int idx  = blockIdx.x * 256 + tid;
        const int lane = idx & 31;
        const int w    = idx >> 5;
        const int uu   = w & (U_ - 1);
        const int b    = w >> 10;
        const float nu   = expf(plog[uu]);
        const float lamC = expf(-(float)CL * nu);
        float* pv = g_v + (size_t)b * NC * U_ + uu;

        const float a0 = pv[(size_t)(2 * lane) * U_];
        const float a1 = pv[(size_t)(2 * lane + 1) * U_];
        float p = fmaf(lamC, a0, a1);
        const float lamC2 = lamC * lamC;

        float mult = lamC2;
        #pragma unroll
        for (int s = 1; s < 32; s <<= 1) {
            float other = __shfl_up_sync(0xffffffffu, p, s);
            if (lane >= s) p = fmaf(mult, other, p);
            mult = mult * mult;
        }

        const float Pprev = __shfl_up_sync(0xffffffffu, p, 1);
        const float E0 = (lane == 0) ? 0.f : Pprev;
        const float E1 = fmaf(lamC, E0, a0);
        pv[(size_t)(2 * lane) * U_]     = E0;
        pv[(size_t)(2 * lane + 1) * U_] = E1;
    }

    grid_bar(&g_cnt[1]);

    // ---- phase 3: redo local scan seeded with carry, * gamma, in place ----
    {
        const int g  = blockIdx.x * 256 + tid;
        const int u2 = g & (U_ / 2 - 1);
        const int c  = (g >> 9) & (NC - 1);
        const int b  = g >> 15;
        const int uu = u2 * 2;
        const float lam0 = expf(-expf(plog[uu]));
        const float lam1 = expf(-expf(plog[uu + 1]));
        const float gam0 = expf(plog[U_ + uu]);
        const float gam1 = expf(plog[U_ + uu + 1]);
        float2 h = reinterpret_cast<const float2*>(
            g_v + (size_t)(b * NC + c) * U_)[u2];
        __half2* p = reinterpret_cast<__half2*>(
            g_uh + (size_t)(b * L_ + c * CL) * U_) + u2;
        #pragma unroll 8
        for (int t = 0; t < CL; t++) {
            float2 v = __half22float2(p[(size_t)t * (U_ / 2)]);
            h.x = fmaf(lam0, h.x, v.x);
            h.y = fmaf(lam1, h.y, v.y);
            p[(size_t)t * (U_ / 2)] = __floats2half2_rn(h.x * gam0, h.y * gam1);
        }
    }
}

// ---------------- launch ------------------------------------------------------
extern "C" void kernel_launch(void* const* d_in, const int* in_sizes, int n_in,
                              void* d_out, int out_size)
{
    const float* inputs = (const float*)d_in[0];
    const float* Wi     = (const float*)d_in[1];
    const float* bi     = (const float*)d_in[2];
    const float* Wo     = (const float*)d_in[3];
    const float* bo     = (const float*)d_in[4];
    const float* plog   = (const float*)d_in[5];
    float* out = (float*)d_out;

    cudaFuncSetAttribute(gemm_f16_kernel,
                         cudaFuncAttributeMaxDynamicSharedMemorySize, GEMM_SMEM);

    // fp16 conversion (also resets the scan grid-barrier counters)
    cvt_all_kernel<<<2048, 256>>>((const float4*)inputs,
                                  (const float4*)Wi,
                                  (const float4*)Wo);

    // GEMM1: u = inputs * Wi^T + bi   -> g_uh (fp16)
    gemm_f16_kernel<<<dim3(U_ / TN, M_ / TM), 256, GEMM_SMEM>>>(0, bi, nullptr);

    // fused scan (agg -> carry -> apply), in place on g_uh
    scan_fused_kernel<<<(B_ * NC * U_ / 2) / 256, 256>>>(plog);

    // GEMM2: out = x * Wo^T + bo
    gemm_f16_kernel<<<dim3(H_ / TN, M_ / TM), 256, GEMM_SMEM>>>(1, bo, out);
}